// round 3
// baseline (speedup 1.0000x reference)
#include <cuda_runtime.h>
#include <math.h>

#define TT    2048
#define BB    2
#define DIMM  2048
#define HEADS 16
#define HD    128
#define INNER 2048
#define NQKV  6144
#define MROWS 4096   // B*T

// Scratch (device globals; no allocations allowed)
__device__ float g_qkv[(size_t)MROWS * NQKV];   // [4096, 6144] q|k|v interleaved
__device__ float g_attn[(size_t)MROWS * INNER]; // [4096, 2048] attention output
__device__ float g_cos[TT * 64];
__device__ float g_sin[TT * 64];

// ---------------------------------------------------------------------------
// RoPE cos/sin tables in fp64 (immune to --use_fast_math trig degradation).
// cos[t*64+j] = cos(t * 10000^(-j/64)), j in [0,64)
// ---------------------------------------------------------------------------
__global__ void table_kernel() {
    int idx = blockIdx.x * 256 + threadIdx.x;   // < 131072
    int j = idx & 63;
    int t = idx >> 6;
    double inv = exp(-log(10000.0) * (double)j / 64.0);
    double ang = (double)t * inv;
    g_cos[idx] = (float)cos(ang);
    g_sin[idx] = (float)sin(ang);
}

// ---------------------------------------------------------------------------
// SGEMM: C[M,N] = A[M,K] @ B[K,N], all row-major fp32.
// 128x128 tile, BK=8, 256 threads, 8x8 microtile. (Exhaustively verified.)
// ---------------------------------------------------------------------------
__global__ __launch_bounds__(256) void sgemm128(
    const float* __restrict__ A, const float* __restrict__ B,
    float* __restrict__ C, int M, int N, int K)
{
    __shared__ float As[8][128];   // transposed: As[k][m]
    __shared__ float Bs[8][128];   // Bs[k][n]

    const int tid = threadIdx.x;
    const int tx  = tid & 15;
    const int ty  = tid >> 4;
    const int bm  = blockIdx.y * 128;
    const int bn  = blockIdx.x * 128;

    const int arow = tid >> 1;
    const int acol = (tid & 1) << 2;
    const int brow = tid >> 5;
    const int bcol = (tid & 31) << 2;

    const float* Ap = A + (size_t)(bm + arow) * K + acol;
    const float* Bp = B + (size_t)brow * N + bn + bcol;

    float acc[8][8];
#pragma unroll
    for (int i = 0; i < 8; i++)
#pragma unroll
        for (int j = 0; j < 8; j++) acc[i][j] = 0.0f;

    float4 a4 = *(const float4*)Ap;
    float4 b4 = *(const float4*)Bp;

    const int nt = K >> 3;
    for (int t = 0; t < nt; ++t) {
        As[acol + 0][arow] = a4.x;
        As[acol + 1][arow] = a4.y;
        As[acol + 2][arow] = a4.z;
        As[acol + 3][arow] = a4.w;
        *(float4*)&Bs[brow][bcol] = b4;
        __syncthreads();

        if (t + 1 < nt) {
            a4 = *(const float4*)(Ap + (size_t)(t + 1) * 8);
            b4 = *(const float4*)(Bp + (size_t)(t + 1) * 8 * N);
        }

#pragma unroll
        for (int kk = 0; kk < 8; ++kk) {
            float4 a0 = *(const float4*)&As[kk][(ty << 2)];
            float4 a1 = *(const float4*)&As[kk][64 + (ty << 2)];
            float4 b0 = *(const float4*)&Bs[kk][(tx << 2)];
            float4 b1 = *(const float4*)&Bs[kk][64 + (tx << 2)];
            float ar[8] = {a0.x, a0.y, a0.z, a0.w, a1.x, a1.y, a1.z, a1.w};
            float br[8] = {b0.x, b0.y, b0.z, b0.w, b1.x, b1.y, b1.z, b1.w};
#pragma unroll
            for (int i = 0; i < 8; i++)
#pragma unroll
                for (int j = 0; j < 8; j++)
                    acc[i][j] = fmaf(ar[i], br[j], acc[i][j]);
        }
        __syncthreads();
    }

#pragma unroll
    for (int i = 0; i < 8; i++) {
        int r = bm + (ty << 2) + (i & 3) + ((i >> 2) << 6);
        float4 c0 = make_float4(acc[i][0], acc[i][1], acc[i][2], acc[i][3]);
        float4 c1 = make_float4(acc[i][4], acc[i][5], acc[i][6], acc[i][7]);
        *(float4*)&C[(size_t)r * N + bn + (tx << 2)]      = c0;
        *(float4*)&C[(size_t)r * N + bn + 64 + (tx << 2)] = c1;
    }
}

// ---------------------------------------------------------------------------
// RoPE in place on q and k sections using the precomputed tables.
// One thread per (m, h, j), j in [0,64); handles q and k, dims j and j+64.
// ---------------------------------------------------------------------------
__global__ __launch_bounds__(256) void rope_kernel(float* __restrict__ qkv)
{
    int idx = blockIdx.x * 256 + threadIdx.x;   // < 4194304
    int j = idx & 63;
    int h = (idx >> 6) & 15;
    int m = idx >> 10;                          // 0..4095
    int t = m & (TT - 1);

    float c = g_cos[t * 64 + j];
    float s = g_sin[t * 64 + j];

    size_t base = (size_t)m * NQKV + h * HD + j;     // q section
    float q1 = qkv[base];
    float q2 = qkv[base + 64];
    qkv[base]      = q1 * c - q2 * s;
    qkv[base + 64] = q2 * c + q1 * s;

    size_t kb = base + INNER;                        // k section
    float k1 = qkv[kb];
    float k2 = qkv[kb + 64];
    qkv[kb]      = k1 * c - k2 * s;
    qkv[kb + 64] = k2 * c + k1 * s;
}

// ---------------------------------------------------------------------------
// Causal attention, one WARP per query row. Online softmax; all state is
// warp-uniform (broadcast via full-warp butterfly reduction). No smem.
// Lane owns dims {lane, lane+32, lane+64, lane+96}.
// Heavy rows (large r) scheduled first via reversed block index.
// ---------------------------------------------------------------------------
__global__ __launch_bounds__(128) void attn_kernel(
    const float* __restrict__ qkv, float* __restrict__ outb)
{
    const int lane = threadIdx.x & 31;
    const int w    = threadIdx.x >> 5;              // warp in block, 0..3
    const int b    = blockIdx.y >> 4;
    const int h    = blockIdx.y & 15;
    const int r    = TT - 1 - (blockIdx.x * 4 + w); // query row, heavy first

    const float scale = 0.08838834764831845f;       // 1/sqrt(128)

    // Load this row's q (pre-scaled)
    const float* qrow = qkv + (size_t)(b * TT + r) * NQKV + h * HD;
    float q0 = qrow[lane]      * scale;
    float q1 = qrow[lane + 32] * scale;
    float q2 = qrow[lane + 64] * scale;
    float q3 = qrow[lane + 96] * scale;

    float m_i = -1.0e30f;
    float l_i = 0.0f;
    float o0 = 0.0f, o1 = 0.0f, o2 = 0.0f, o3 = 0.0f;

    const float* kbase = qkv + (size_t)(b * TT) * NQKV + INNER     + h * HD;
    const float* vbase = qkv + (size_t)(b * TT) * NQKV + 2 * INNER + h * HD;

    for (int k = 0; k <= r; ++k) {
        const float* kr = kbase + (size_t)k * NQKV;
        float part = q0 * kr[lane]
                   + q1 * kr[lane + 32]
                   + q2 * kr[lane + 64]
                   + q3 * kr[lane + 96];
        // full-warp sum -> every lane holds s
        part += __shfl_xor_sync(0xffffffffu, part, 1);
        part += __shfl_xor_sync(0xffffffffu, part, 2);
        part += __shfl_xor_sync(0xffffffffu, part, 4);
        part += __shfl_xor_sync(0xffffffffu, part, 8);
        part += __shfl_xor_sync(0xffffffffu, part, 16);
        float s = part;

        float mn    = fmaxf(m_i, s);
        float alpha = expf(m_i - mn);
        float p     = expf(s - mn);
        m_i = mn;
        l_i = l_i * alpha + p;

        const float* vr = vbase + (size_t)k * NQKV;
        o0 = o0 * alpha + p * vr[lane];
        o1 = o1 * alpha + p * vr[lane + 32];
        o2 = o2 * alpha + p * vr[lane + 64];
        o3 = o3 * alpha + p * vr[lane + 96];
    }

    float inv = 1.0f / l_i;
    float* orow = outb + (size_t)(b * TT + r) * INNER + h * HD;
    orow[lane]      = o0 * inv;
    orow[lane + 32] = o1 * inv;
    orow[lane + 64] = o2 * inv;
    orow[lane + 96] = o3 * inv;
}

// ---------------------------------------------------------------------------
// Entry point. Inputs selected by element count OR byte count, falling back
// to positional order (x, w_qkv, w_out).
// ---------------------------------------------------------------------------
extern "C" void kernel_launch(void* const* d_in, const int* in_sizes, int n_in,
                              void* d_out, int out_size)
{
    (void)out_size;
    const int NX = BB * TT * DIMM;   // 8388608
    const int NW = DIMM * NQKV;      // 12582912
    const int NO = INNER * DIMM;     // 4194304

    const float* x     = nullptr;
    const float* w_qkv = nullptr;
    const float* w_out = nullptr;
    for (int i = 0; i < n_in; ++i) {
        int sz = in_sizes[i];
        if      (sz == NX || sz == NX * 4) x     = (const float*)d_in[i];
        else if (sz == NW || sz == NW * 4) w_qkv = (const float*)d_in[i];
        else if (sz == NO || sz == NO * 4) w_out = (const float*)d_in[i];
    }
    if (!x || !w_qkv || !w_out) {   // positional fallback
        x     = (const float*)d_in[0];
        w_qkv = (const float*)d_in[1];
        w_out = (const float*)d_in[2];
    }

    float* out = (float*)d_out;

    float* qkv_p  = nullptr;
    float* attn_p = nullptr;
    cudaGetSymbolAddress((void**)&qkv_p, g_qkv);
    cudaGetSymbolAddress((void**)&attn_p, g_attn);

    // 1. RoPE tables (fp64)
    table_kernel<<<(TT * 64) / 256, 256>>>();

    // 2. QKV projection: [4096,2048] @ [2048,6144]
    sgemm128<<<dim3(NQKV / 128, MROWS / 128), 256>>>(x, w_qkv, qkv_p,
                                                     MROWS, NQKV, DIMM);

    // 3. RoPE in place on q and k
    rope_kernel<<<(MROWS * HEADS * 64) / 256, 256>>>(qkv_p);

    // 4. Causal attention (one warp per query row)
    attn_kernel<<<dim3(TT / 4, BB * HEADS), 128>>>(qkv_p, attn_p);

    // 5. Output projection: [4096,2048] @ [2048,2048] -> d_out
    sgemm128<<<dim3(DIMM / 128, MROWS / 128), 256>>>(attn_p, w_out, out,
                                                     MROWS, DIMM, INNER);
}